// round 3
// baseline (speedup 1.0000x reference)
#include <cuda_runtime.h>
#include <math.h>

// ---------------------------------------------------------------------------
// Problem constants (shapes fixed by setup_inputs)
// ---------------------------------------------------------------------------
#define SEQ    4096
#define DM     1024
#define NIMU   72
#define NNOISE 12
#define NOUT   (NIMU * NNOISE)   // 864
#define TSTEPS 300
#define NM     (NIMU * SEQ)      // 294912

// ---------------------------------------------------------------------------
// Scratch (static device globals; no allocation allowed)
// ---------------------------------------------------------------------------
__device__ float  g_mu[SEQ];
__device__ float  g_rstd[SEQ];
__device__ float  g_gamma[DM];
__device__ float  g_beta[DM];
__device__ float  g_bprime[NOUT];
__device__ float  g_p[SEQ * NOUT];           // 14.2 MB
__device__ float2 g_X0[NM], g_Y0[NM], g_A[NM], g_B[NM];   // 9.4 MB

// ---------------------------------------------------------------------------
// f32x2 packed helpers (Blackwell FFMA2 — only reachable via PTX)
// ---------------------------------------------------------------------------
typedef unsigned long long ull;

__device__ __forceinline__ ull pk2(float lo, float hi) {
    ull r;
    asm("mov.b64 %0, {%1, %2};" : "=l"(r) : "f"(lo), "f"(hi));
    return r;
}
__device__ __forceinline__ void upk2(float& lo, float& hi, ull v) {
    asm("mov.b64 {%0, %1}, %2;" : "=f"(lo), "=f"(hi) : "l"(v));
}
#define FMA2(d, a, b, c) asm("fma.rn.f32x2 %0, %1, %2, %3;" : "=l"(d) : "l"(a), "l"(b), "l"(c))
#define MUL2(d, a, b)    asm("mul.rn.f32x2 %0, %1, %2;"     : "=l"(d) : "l"(a), "l"(b))

__device__ __forceinline__ float softplus_f(float x) {
    // matches jax.nn.softplus: max(x,0) + log1p(exp(-|x|))
    return fmaxf(x, 0.0f) + log1pf(expf(-fabsf(x)));
}

// ---------------------------------------------------------------------------
// 0) Disambiguate the two 1024-length LN vectors (gamma≈ones, beta≈zeros).
// ---------------------------------------------------------------------------
__global__ __launch_bounds__(256) void pick_ln_kernel(const float* __restrict__ a,
                                                      const float* __restrict__ b) {
    __shared__ float sA, sB;
    const int tid = threadIdx.x;
    if (tid == 0) { sA = 0.0f; sB = 0.0f; }
    __syncthreads();
    float la = 0.0f, lb = 0.0f;
    for (int k = tid; k < DM; k += 256) {
        float av = a[k], bv = b[k];
        la += (av - 1.0f) * (av - 1.0f) + bv * bv;        // hypothesis: a=gamma
        lb += (bv - 1.0f) * (bv - 1.0f) + av * av;        // hypothesis: b=gamma
    }
    #pragma unroll
    for (int o = 16; o > 0; o >>= 1) {
        la += __shfl_down_sync(0xffffffffu, la, o);
        lb += __shfl_down_sync(0xffffffffu, lb, o);
    }
    if ((tid & 31) == 0) { atomicAdd(&sA, la); atomicAdd(&sB, lb); }
    __syncthreads();
    const bool swap = sB < sA;
    for (int k = tid; k < DM; k += 256) {
        g_gamma[k] = swap ? b[k] : a[k];
        g_beta[k]  = swap ? a[k] : b[k];
    }
}

// ---------------------------------------------------------------------------
// 1) Per-token mean / rstd
// ---------------------------------------------------------------------------
__global__ __launch_bounds__(256) void stats_kernel(const float* __restrict__ x) {
    __shared__ float ss[8], ss2[8];
    const int row = blockIdx.x;
    const int tid = threadIdx.x;
    float4 v = reinterpret_cast<const float4*>(x + (size_t)row * DM)[tid];
    float s  = v.x + v.y + v.z + v.w;
    float s2 = v.x * v.x + v.y * v.y + v.z * v.z + v.w * v.w;
    #pragma unroll
    for (int o = 16; o > 0; o >>= 1) {
        s  += __shfl_down_sync(0xffffffffu, s,  o);
        s2 += __shfl_down_sync(0xffffffffu, s2, o);
    }
    if ((tid & 31) == 0) { ss[tid >> 5] = s; ss2[tid >> 5] = s2; }
    __syncthreads();
    if (tid < 8) {
        s = ss[tid]; s2 = ss2[tid];
        #pragma unroll
        for (int o = 4; o > 0; o >>= 1) {
            s  += __shfl_down_sync(0xffu, s,  o);
            s2 += __shfl_down_sync(0xffu, s2, o);
        }
        if (tid == 0) {
            float mu  = s * (1.0f / DM);
            float var = s2 * (1.0f / DM) - mu * mu;
            g_mu[row]   = mu;
            g_rstd[row] = 1.0f / sqrtf(var + 1e-5f);
        }
    }
}

// ---------------------------------------------------------------------------
// 2) bprime[n] = b[n] + sum_k beta[k] * W[k][n]
// ---------------------------------------------------------------------------
__global__ __launch_bounds__(256) void bprime_kernel(const float* __restrict__ W,
                                                     const float* __restrict__ b) {
    int n = blockIdx.x * 256 + threadIdx.x;
    if (n >= NOUT) return;
    float acc = b[n];
    for (int k = 0; k < DM; k++) acc = fmaf(g_beta[k], W[(size_t)k * NOUT + n], acc);
    g_bprime[n] = acc;
}

// ---------------------------------------------------------------------------
// 3) GEMM with fused LN on A:  p = ((x-mu)*rstd*gamma) @ W + bprime
// ---------------------------------------------------------------------------
#define BM 128
#define BN 32
#define BK 16

__global__ __launch_bounds__(256) void gemm_kernel(const float* __restrict__ x,
                                                   const float* __restrict__ W) {
    __shared__ float As[BK][BM];
    __shared__ float Bs[BK][BN];

    const int bm  = blockIdx.x * BM;
    const int bn  = blockIdx.y * BN;
    const int tid = threadIdx.x;
    const int tm  = tid >> 4;   // 0..15 -> rows tm*8 .. tm*8+7
    const int tn  = tid & 15;   // 0..15 -> cols tn*2, tn*2+1

    ull a00 = 0, a01 = 0, a10 = 0, a11 = 0, a20 = 0, a21 = 0, a30 = 0, a31 = 0;

    for (int k0 = 0; k0 < DM; k0 += BK) {
        #pragma unroll
        for (int l = 0; l < 2; l++) {
            int f  = tid + l * 256;         // 0..511
            int m  = f >> 2;                // 0..127
            int kk = (f & 3) << 2;          // 0,4,8,12
            float4 xv = *reinterpret_cast<const float4*>(x + (size_t)(bm + m) * DM + k0 + kk);
            float4 gv = *reinterpret_cast<const float4*>(&g_gamma[k0 + kk]);
            float mu = g_mu[bm + m];
            float rs = g_rstd[bm + m];
            As[kk + 0][m] = (xv.x - mu) * rs * gv.x;
            As[kk + 1][m] = (xv.y - mu) * rs * gv.y;
            As[kk + 2][m] = (xv.z - mu) * rs * gv.z;
            As[kk + 3][m] = (xv.w - mu) * rs * gv.w;
        }
        #pragma unroll
        for (int l = 0; l < 2; l++) {
            int e  = tid + l * 256;
            int kk = e >> 5, nn = e & 31;
            Bs[kk][nn] = W[(size_t)(k0 + kk) * NOUT + bn + nn];
        }
        __syncthreads();

        #pragma unroll
        for (int k = 0; k < BK; k++) {
            const ull* ar = reinterpret_cast<const ull*>(&As[k][tm * 8]);
            ull r0 = ar[0], r1 = ar[1], r2 = ar[2], r3 = ar[3];
            float2 bv = *reinterpret_cast<const float2*>(&Bs[k][tn * 2]);
            ull b0 = pk2(bv.x, bv.x);
            ull b1 = pk2(bv.y, bv.y);
            FMA2(a00, r0, b0, a00); FMA2(a01, r0, b1, a01);
            FMA2(a10, r1, b0, a10); FMA2(a11, r1, b1, a11);
            FMA2(a20, r2, b0, a20); FMA2(a21, r2, b1, a21);
            FMA2(a30, r3, b0, a30); FMA2(a31, r3, b1, a31);
        }
        __syncthreads();
    }

    const int col = bn + tn * 2;
    const float bp0 = g_bprime[col];
    const float bp1 = g_bprime[col + 1];
    const int row0 = bm + tm * 8;
    ull accs[4][2] = {{a00, a01}, {a10, a11}, {a20, a21}, {a30, a31}};
    #pragma unroll
    for (int r2 = 0; r2 < 4; r2++) {
        float c0lo, c0hi, c1lo, c1hi;
        upk2(c0lo, c0hi, accs[r2][0]);
        upk2(c1lo, c1hi, accs[r2][1]);
        int r = row0 + r2 * 2;
        float2 v0 = make_float2(c0lo + bp0, c1lo + bp1);
        float2 v1 = make_float2(c0hi + bp0, c1hi + bp1);
        *reinterpret_cast<float2*>(&g_p[(size_t)r * NOUT + col])       = v0;
        *reinterpret_cast<float2*>(&g_p[(size_t)(r + 1) * NOUT + col]) = v1;
    }
}

// ---------------------------------------------------------------------------
// 4) Epilogue: derive spring recurrence params + 4 transposed output channels
// ---------------------------------------------------------------------------
__global__ __launch_bounds__(256) void epi_kernel(float* __restrict__ out, int full_out) {
    int j = blockIdx.x * 256 + threadIdx.x;
    if (j >= NM) return;
    int s = j & (SEQ - 1);
    int i = j >> 12;
    const float* pr = g_p + (size_t)s * NOUT;
    float p0  = __ldg(pr + 0 * NIMU + i);
    float p1  = __ldg(pr + 1 * NIMU + i);
    float p2  = __ldg(pr + 2 * NIMU + i);
    float p3  = __ldg(pr + 3 * NIMU + i);
    float c   = __ldg(pr + 4 * NIMU + i);
    float ct  = __ldg(pr + 5 * NIMU + i);
    float phi = __ldg(pr + 6 * NIMU + i);
    float pht = __ldg(pr + 7 * NIMU + i);
    float p8  = __ldg(pr + 8 * NIMU + i);
    float p9  = __ldg(pr + 9 * NIMU + i);
    float p10 = __ldg(pr + 10 * NIMU + i);
    float p11 = __ldg(pr + 11 * NIMU + i);

    float d  = softplus_f(p1);
    float dt = softplus_f(p3);
    float w1 = sqrtf(softplus_f(p0));   // sqrt(4k - d^2)/2 with k = d^2/4 + sp(p0)
    float w2 = sqrtf(softplus_f(p2));
    float e1 = expf(-0.5f * d);
    float e2 = expf(-0.5f * dt);

    float sph, cph, spt, cpt, sw1, cw1, sw2, cw2;
    sincosf(phi, &sph, &cph);
    sincosf(pht, &spt, &cpt);
    sincosf(w1, &sw1, &cw1);
    sincosf(w2, &sw2, &cw2);

    g_X0[j] = make_float2(c * cph, ct * cpt);
    g_Y0[j] = make_float2(c * sph, ct * spt);
    g_A[j]  = make_float2(e1 * cw1, e2 * cw2);
    g_B[j]  = make_float2(e1 * sw1, e2 * sw2);

    if (full_out) {
        out[1 * NM + j] = p8;               // acc_base
        out[2 * NM + j] = softplus_f(p9);   // acc_std
        out[3 * NM + j] = p10;              // gyro_base
        out[4 * NM + j] = softplus_f(p11);  // gyro_std
    }
}

// ---------------------------------------------------------------------------
// 5) Zero kinematics region
// ---------------------------------------------------------------------------
__global__ __launch_bounds__(256) void zero_kernel(float* __restrict__ out) {
    int j = blockIdx.x * 256 + threadIdx.x;
    if (j < NM) out[j] = 0.0f;
}

// ---------------------------------------------------------------------------
// 6) Spring + diagonal scatter — ROTATING-ACCUMULATOR WAVEFRONT (race-free).
//    Warp owns 32 consecutive tokens. At step t, the contribution of lane
//    (j - t) mod 32 targets block-local position j + 32q; each lane keeps a
//    register accumulator and receives its contribution via one shfl rotate.
//    Position p completes at step p+1 and is flushed by the unique lane
//    (t-1)&31, so every sbuf entry is written EXACTLY ONCE. No shared RMW.
// ---------------------------------------------------------------------------
__global__ __launch_bounds__(256) void spring_kernel(float* __restrict__ out) {
    __shared__ float sbuf[8][336];   // 331 used per warp

    const int i    = blockIdx.y;
    const int s0   = blockIdx.x * 256;
    const int tid  = threadIdx.x;
    const int w    = tid >> 5;
    const int lane = tid & 31;

    const int s   = s0 + w * 32 + lane;
    const int idx = i * SEQ + s;
    float2 x0 = g_X0[idx], y0 = g_Y0[idx], av = g_A[idx], bv = g_B[idx];
    ull X  = pk2(x0.x, x0.y);
    ull Y  = pk2(y0.x, y0.y);
    ull A  = pk2(av.x, av.y);
    ull B  = pk2(bv.x, bv.y);
    ull Bn = pk2(-bv.x, -bv.y);

    float* buf = &sbuf[w][0];
    float acc = 0.0f;
    int   src = lane;     // (lane - t) & 31
    int   fl  = -1;       // (t - 1) & 31 ; no flush at t = 0

    #pragma unroll 4
    for (int t = 0; t < TSTEPS; t++) {
        float lo, hi;
        upk2(lo, hi, Y);
        float c = lo + hi;                       // lin + ang of own token at step t
        float r = __shfl_sync(0xffffffffu, c, src);
        if (fl == lane) { buf[t - 1] = acc; acc = 0.0f; }
        acc += r;
        // recurrence: Z <- Z * (A + iB), packed lin/ang
        ull u, v, Xn;
        MUL2(u, Y, Bn);        // -Y*B
        FMA2(Xn, X, A, u);     // X*A - Y*B
        MUL2(v, X, B);         //  X*B
        FMA2(Y, Y, A, v);      // Y*A + X*B
        X = Xn;
        src = (src + 31) & 31;
        fl  = (fl + 1) & 31;
    }
    // Final flush: lane j holds position p = 299 + ((j - 11) & 31), p in [299,330]
    {
        int p = (TSTEPS - 1) + ((lane - ((TSTEPS - 1) & 31)) & 31);
        buf[p] = acc;
    }
    __syncthreads();

    // Block-level merge of overlapping warp buffers, then one atomic pass.
    // Warp w covers block-local positions [32w, 32w+330]; span = [0, 554].
    for (int q = tid; q < 555; q += 256) {
        float tot = 0.0f;
        #pragma unroll
        for (int w2 = 0; w2 < 8; w2++) {
            int r = q - 32 * w2;
            if (r >= 0 && r < 331) tot += sbuf[w2][r];
        }
        int pos = s0 + q;
        if (pos < SEQ) atomicAdd(&out[i * SEQ + pos], tot);
    }
}

// ---------------------------------------------------------------------------
// Launch — inputs identified by size:
//   hidden_states: 4194304, W: 884736, b: 864, ln_gamma/ln_beta: 1024 (x2)
// ---------------------------------------------------------------------------
extern "C" void kernel_launch(void* const* d_in, const int* in_sizes, int n_in,
                              void* d_out, int out_size) {
    const float* x  = nullptr;
    const float* W  = nullptr;
    const float* b  = nullptr;
    const float* v1 = nullptr;
    const float* v2 = nullptr;
    for (int idx = 0; idx < n_in; idx++) {
        int sz = in_sizes[idx];
        const float* p = (const float*)d_in[idx];
        if      (sz == SEQ * DM)   x = p;
        else if (sz == DM * NOUT)  W = p;
        else if (sz == NOUT)       b = p;
        else if (sz == DM)         { if (!v1) v1 = p; else v2 = p; }
    }
    float* out = (float*)d_out;
    int full_out = (out_size >= 5 * NM) ? 1 : 0;

    pick_ln_kernel<<<1, 256>>>(v1, v2);
    stats_kernel<<<SEQ, 256>>>(x);
    bprime_kernel<<<(NOUT + 255) / 256, 256>>>(W, b);
    gemm_kernel<<<dim3(SEQ / BM, NOUT / BN), 256>>>(x, W);
    epi_kernel<<<(NM + 255) / 256, 256>>>(out, full_out);
    zero_kernel<<<(NM + 255) / 256, 256>>>(out);
    spring_kernel<<<dim3(SEQ / 256, NIMU), 256>>>(out);
}

// round 4
// speedup vs baseline: 1.4868x; 1.4868x over previous
#include <cuda_runtime.h>
#include <math.h>

// ---------------------------------------------------------------------------
// Problem constants (shapes fixed by setup_inputs)
// ---------------------------------------------------------------------------
#define SEQ    4096
#define DM     1024
#define NIMU   72
#define NNOISE 12
#define NOUT   (NIMU * NNOISE)   // 864
#define TSTEPS 300
#define NM     (NIMU * SEQ)      // 294912

// ---------------------------------------------------------------------------
// Scratch (static device globals; no allocation allowed)
// ---------------------------------------------------------------------------
__device__ float  g_mu[SEQ];
__device__ float  g_rstd[SEQ];
__device__ float  g_gamma[DM];
__device__ float  g_beta[DM];
__device__ float  g_bprime[NOUT];
__device__ float  g_p[SEQ * NOUT];           // 14.2 MB
__device__ float2 g_X0[NM], g_Y0[NM], g_A[NM], g_B[NM];   // 9.4 MB

// ---------------------------------------------------------------------------
// f32x2 packed helpers (Blackwell FFMA2 — only reachable via PTX)
// ---------------------------------------------------------------------------
typedef unsigned long long ull;

__device__ __forceinline__ ull pk2(float lo, float hi) {
    ull r;
    asm("mov.b64 %0, {%1, %2};" : "=l"(r) : "f"(lo), "f"(hi));
    return r;
}
__device__ __forceinline__ void upk2(float& lo, float& hi, ull v) {
    asm("mov.b64 {%0, %1}, %2;" : "=f"(lo), "=f"(hi) : "l"(v));
}
#define FMA2(d, a, b, c) asm("fma.rn.f32x2 %0, %1, %2, %3;" : "=l"(d) : "l"(a), "l"(b), "l"(c))
#define MUL2(d, a, b)    asm("mul.rn.f32x2 %0, %1, %2;"     : "=l"(d) : "l"(a), "l"(b))

__device__ __forceinline__ float softplus_f(float x) {
    return fmaxf(x, 0.0f) + log1pf(expf(-fabsf(x)));
}

// ---------------------------------------------------------------------------
// 0) Disambiguate the two 1024-length LN vectors (gamma≈ones, beta≈zeros).
// ---------------------------------------------------------------------------
__global__ __launch_bounds__(256) void pick_ln_kernel(const float* __restrict__ a,
                                                      const float* __restrict__ b) {
    __shared__ float sA, sB;
    const int tid = threadIdx.x;
    if (tid == 0) { sA = 0.0f; sB = 0.0f; }
    __syncthreads();
    float la = 0.0f, lb = 0.0f;
    for (int k = tid; k < DM; k += 256) {
        float av = a[k], bv = b[k];
        la += (av - 1.0f) * (av - 1.0f) + bv * bv;
        lb += (bv - 1.0f) * (bv - 1.0f) + av * av;
    }
    #pragma unroll
    for (int o = 16; o > 0; o >>= 1) {
        la += __shfl_down_sync(0xffffffffu, la, o);
        lb += __shfl_down_sync(0xffffffffu, lb, o);
    }
    if ((tid & 31) == 0) { atomicAdd(&sA, la); atomicAdd(&sB, lb); }
    __syncthreads();
    const bool swap = sB < sA;
    for (int k = tid; k < DM; k += 256) {
        g_gamma[k] = swap ? b[k] : a[k];
        g_beta[k]  = swap ? a[k] : b[k];
    }
}

// ---------------------------------------------------------------------------
// 1) Per-token mean / rstd
// ---------------------------------------------------------------------------
__global__ __launch_bounds__(256) void stats_kernel(const float* __restrict__ x) {
    __shared__ float ss[8], ss2[8];
    const int row = blockIdx.x;
    const int tid = threadIdx.x;
    float4 v = reinterpret_cast<const float4*>(x + (size_t)row * DM)[tid];
    float s  = v.x + v.y + v.z + v.w;
    float s2 = v.x * v.x + v.y * v.y + v.z * v.z + v.w * v.w;
    #pragma unroll
    for (int o = 16; o > 0; o >>= 1) {
        s  += __shfl_down_sync(0xffffffffu, s,  o);
        s2 += __shfl_down_sync(0xffffffffu, s2, o);
    }
    if ((tid & 31) == 0) { ss[tid >> 5] = s; ss2[tid >> 5] = s2; }
    __syncthreads();
    if (tid < 8) {
        s = ss[tid]; s2 = ss2[tid];
        #pragma unroll
        for (int o = 4; o > 0; o >>= 1) {
            s  += __shfl_down_sync(0xffu, s,  o);
            s2 += __shfl_down_sync(0xffu, s2, o);
        }
        if (tid == 0) {
            float mu  = s * (1.0f / DM);
            float var = s2 * (1.0f / DM) - mu * mu;
            g_mu[row]   = mu;
            g_rstd[row] = 1.0f / sqrtf(var + 1e-5f);
        }
    }
}

// ---------------------------------------------------------------------------
// 2) bprime[n] = b[n] + sum_k beta[k] * W[k][n]
//    27 blocks x 256 threads; 8 warps split the k-dim, smem reduce.
// ---------------------------------------------------------------------------
__global__ __launch_bounds__(256) void bprime_kernel(const float* __restrict__ W,
                                                     const float* __restrict__ b) {
    __shared__ float sred[8][32];
    const int tid  = threadIdx.x;
    const int lane = tid & 31;
    const int w    = tid >> 5;
    const int col  = blockIdx.x * 32 + lane;
    float acc = 0.0f;
    #pragma unroll 8
    for (int k = w; k < DM; k += 8)
        acc = fmaf(g_beta[k], W[(size_t)k * NOUT + col], acc);
    sred[w][lane] = acc;
    __syncthreads();
    if (w == 0) {
        float tot = b[col];
        #pragma unroll
        for (int j = 0; j < 8; j++) tot += sred[j][lane];
        g_bprime[col] = tot;
    }
}

// ---------------------------------------------------------------------------
// 3) GEMM with fused LN on A:  p = ((x-mu)*rstd*gamma) @ W + bprime
//    BM=128, BN=96, BK=32, 256 threads, 8x6 thread tile, FFMA2 over M-pairs,
//    double-buffered smem, register-prefetched global loads, 1 bar/iter.
// ---------------------------------------------------------------------------
#define BM 128
#define BN 96
#define BK 32
#define NITER (DM / BK)   // 32

__global__ __launch_bounds__(256) void gemm_kernel(const float* __restrict__ x,
                                                   const float* __restrict__ W) {
    __shared__ __align__(16) float As[2][BK][BM + 2];
    __shared__ __align__(16) float Bs[2][BK][BN];

    const int bm  = blockIdx.x * BM;
    const int bn  = blockIdx.y * BN;
    const int tid = threadIdx.x;
    const int tm  = tid >> 4;          // 0..15 -> rows tm*8..+7
    const int tn  = tid & 15;          // 0..15 -> cols tn*6..+5

    // loader mapping
    const int am = tid >> 3;           // A base row (+32*l), l=0..3
    const int ak = (tid & 7) * 4;      // A k-offset (4 consecutive k)
    const int bk = tid >> 3;           // B row (k)
    const int bc = (tid & 7) * 4;      // B col base (+32*l), l=0..2

    float mu[4], rs[4];
    #pragma unroll
    for (int l = 0; l < 4; l++) {
        mu[l] = g_mu[bm + am + 32 * l];
        rs[l] = g_rstd[bm + am + 32 * l];
    }

    float4 ra[4], rb[3], g4;

    #define LOADG(IT) do {                                                      \
        const float* xp = x + (size_t)(bm + am) * DM + (IT) * BK + ak;          \
        ra[0] = *(const float4*)(xp);                                           \
        ra[1] = *(const float4*)(xp + 32 * DM);                                 \
        ra[2] = *(const float4*)(xp + 64 * DM);                                 \
        ra[3] = *(const float4*)(xp + 96 * DM);                                 \
        const float* wp = W + (size_t)((IT) * BK + bk) * NOUT + bn + bc;        \
        rb[0] = *(const float4*)(wp);                                           \
        rb[1] = *(const float4*)(wp + 32);                                      \
        rb[2] = *(const float4*)(wp + 64);                                      \
        g4 = *(const float4*)&g_gamma[(IT) * BK + ak];                          \
    } while (0)

    #define STORES(NB) do {                                                     \
        _Pragma("unroll")                                                       \
        for (int l = 0; l < 4; l++) {                                           \
            int m = am + 32 * l;                                                \
            As[NB][ak + 0][m] = (ra[l].x - mu[l]) * rs[l] * g4.x;               \
            As[NB][ak + 1][m] = (ra[l].y - mu[l]) * rs[l] * g4.y;               \
            As[NB][ak + 2][m] = (ra[l].z - mu[l]) * rs[l] * g4.z;               \
            As[NB][ak + 3][m] = (ra[l].w - mu[l]) * rs[l] * g4.w;               \
        }                                                                       \
        *(float4*)&Bs[NB][bk][bc]      = rb[0];                                 \
        *(float4*)&Bs[NB][bk][bc + 32] = rb[1];                                 \
        *(float4*)&Bs[NB][bk][bc + 64] = rb[2];                                 \
    } while (0)

    ull acc[4][6];
    #pragma unroll
    for (int r = 0; r < 4; r++)
        #pragma unroll
        for (int j = 0; j < 6; j++) acc[r][j] = 0;

    LOADG(0);
    STORES(0);
    __syncthreads();

    for (int it = 0; it < NITER; it++) {
        const int cur = it & 1;
        if (it + 1 < NITER) LOADG(it + 1);

        #pragma unroll 8
        for (int k = 0; k < BK; k++) {
            const ull* ar = (const ull*)&As[cur][k][tm * 8];
            ull a0 = ar[0], a1 = ar[1], a2 = ar[2], a3 = ar[3];
            const float* bp = &Bs[cur][k][tn * 6];
            float2 b01 = *(const float2*)(bp);
            float2 b23 = *(const float2*)(bp + 2);
            float2 b45 = *(const float2*)(bp + 4);
            ull bb0 = pk2(b01.x, b01.x), bb1 = pk2(b01.y, b01.y);
            ull bb2 = pk2(b23.x, b23.x), bb3 = pk2(b23.y, b23.y);
            ull bb4 = pk2(b45.x, b45.x), bb5 = pk2(b45.y, b45.y);
            FMA2(acc[0][0], a0, bb0, acc[0][0]); FMA2(acc[0][1], a0, bb1, acc[0][1]);
            FMA2(acc[0][2], a0, bb2, acc[0][2]); FMA2(acc[0][3], a0, bb3, acc[0][3]);
            FMA2(acc[0][4], a0, bb4, acc[0][4]); FMA2(acc[0][5], a0, bb5, acc[0][5]);
            FMA2(acc[1][0], a1, bb0, acc[1][0]); FMA2(acc[1][1], a1, bb1, acc[1][1]);
            FMA2(acc[1][2], a1, bb2, acc[1][2]); FMA2(acc[1][3], a1, bb3, acc[1][3]);
            FMA2(acc[1][4], a1, bb4, acc[1][4]); FMA2(acc[1][5], a1, bb5, acc[1][5]);
            FMA2(acc[2][0], a2, bb0, acc[2][0]); FMA2(acc[2][1], a2, bb1, acc[2][1]);
            FMA2(acc[2][2], a2, bb2, acc[2][2]); FMA2(acc[2][3], a2, bb3, acc[2][3]);
            FMA2(acc[2][4], a2, bb4, acc[2][4]); FMA2(acc[2][5], a2, bb5, acc[2][5]);
            FMA2(acc[3][0], a3, bb0, acc[3][0]); FMA2(acc[3][1], a3, bb1, acc[3][1]);
            FMA2(acc[3][2], a3, bb2, acc[3][2]); FMA2(acc[3][3], a3, bb3, acc[3][3]);
            FMA2(acc[3][4], a3, bb4, acc[3][4]); FMA2(acc[3][5], a3, bb5, acc[3][5]);
        }

        if (it + 1 < NITER) STORES((it + 1) & 1);
        __syncthreads();
    }

    // Epilogue: add bprime, store 6 cols x 8 rows
    const int col = bn + tn * 6;
    float bpv[6];
    #pragma unroll
    for (int j = 0; j < 6; j++) bpv[j] = g_bprime[col + j];

    #pragma unroll
    for (int r = 0; r < 4; r++) {
        float lo[6], hi[6];
        #pragma unroll
        for (int j = 0; j < 6; j++) {
            upk2(lo[j], hi[j], acc[r][j]);
            lo[j] += bpv[j];
            hi[j] += bpv[j];
        }
        const int row = bm + tm * 8 + 2 * r;
        float* o0 = &g_p[(size_t)row * NOUT + col];
        float* o1 = o0 + NOUT;
        *(float2*)(o0)     = make_float2(lo[0], lo[1]);
        *(float2*)(o0 + 2) = make_float2(lo[2], lo[3]);
        *(float2*)(o0 + 4) = make_float2(lo[4], lo[5]);
        *(float2*)(o1)     = make_float2(hi[0], hi[1]);
        *(float2*)(o1 + 2) = make_float2(hi[2], hi[3]);
        *(float2*)(o1 + 4) = make_float2(hi[4], hi[5]);
    }
    #undef LOADG
    #undef STORES
}

// ---------------------------------------------------------------------------
// 4) Epilogue: derive spring recurrence params + 4 transposed output channels
// ---------------------------------------------------------------------------
__global__ __launch_bounds__(256) void epi_kernel(float* __restrict__ out, int full_out) {
    int j = blockIdx.x * 256 + threadIdx.x;
    if (j >= NM) return;
    int s = j & (SEQ - 1);
    int i = j >> 12;
    const float* pr = g_p + (size_t)s * NOUT;
    float p0  = __ldg(pr + 0 * NIMU + i);
    float p1  = __ldg(pr + 1 * NIMU + i);
    float p2  = __ldg(pr + 2 * NIMU + i);
    float p3  = __ldg(pr + 3 * NIMU + i);
    float c   = __ldg(pr + 4 * NIMU + i);
    float ct  = __ldg(pr + 5 * NIMU + i);
    float phi = __ldg(pr + 6 * NIMU + i);
    float pht = __ldg(pr + 7 * NIMU + i);
    float p8  = __ldg(pr + 8 * NIMU + i);
    float p9  = __ldg(pr + 9 * NIMU + i);
    float p10 = __ldg(pr + 10 * NIMU + i);
    float p11 = __ldg(pr + 11 * NIMU + i);

    float d  = softplus_f(p1);
    float dt = softplus_f(p3);
    float w1 = sqrtf(softplus_f(p0));
    float w2 = sqrtf(softplus_f(p2));
    float e1 = expf(-0.5f * d);
    float e2 = expf(-0.5f * dt);

    float sph, cph, spt, cpt, sw1, cw1, sw2, cw2;
    sincosf(phi, &sph, &cph);
    sincosf(pht, &spt, &cpt);
    sincosf(w1, &sw1, &cw1);
    sincosf(w2, &sw2, &cw2);

    g_X0[j] = make_float2(c * cph, ct * cpt);
    g_Y0[j] = make_float2(c * sph, ct * spt);
    g_A[j]  = make_float2(e1 * cw1, e2 * cw2);
    g_B[j]  = make_float2(e1 * sw1, e2 * sw2);

    if (full_out) {
        out[1 * NM + j] = p8;
        out[2 * NM + j] = softplus_f(p9);
        out[3 * NM + j] = p10;
        out[4 * NM + j] = softplus_f(p11);
    }
}

// ---------------------------------------------------------------------------
// 5) Zero kinematics region
// ---------------------------------------------------------------------------
__global__ __launch_bounds__(256) void zero_kernel(float* __restrict__ out) {
    int j = blockIdx.x * 256 + threadIdx.x;
    if (j < NM) out[j] = 0.0f;
}

// ---------------------------------------------------------------------------
// 6) Spring + diagonal scatter — rotating-accumulator wavefront (race-free).
// ---------------------------------------------------------------------------
__global__ __launch_bounds__(256) void spring_kernel(float* __restrict__ out) {
    __shared__ float sbuf[8][336];

    const int i    = blockIdx.y;
    const int s0   = blockIdx.x * 256;
    const int tid  = threadIdx.x;
    const int w    = tid >> 5;
    const int lane = tid & 31;

    const int s   = s0 + w * 32 + lane;
    const int idx = i * SEQ + s;
    float2 x0 = g_X0[idx], y0 = g_Y0[idx], av = g_A[idx], bv = g_B[idx];
    ull X  = pk2(x0.x, x0.y);
    ull Y  = pk2(y0.x, y0.y);
    ull A  = pk2(av.x, av.y);
    ull B  = pk2(bv.x, bv.y);
    ull Bn = pk2(-bv.x, -bv.y);

    float* buf = &sbuf[w][0];
    float acc = 0.0f;
    int   src = lane;
    int   fl  = -1;

    #pragma unroll 4
    for (int t = 0; t < TSTEPS; t++) {
        float lo, hi;
        upk2(lo, hi, Y);
        float c = lo + hi;
        float r = __shfl_sync(0xffffffffu, c, src);
        if (fl == lane) { buf[t - 1] = acc; acc = 0.0f; }
        acc += r;
        ull u, v, Xn;
        MUL2(u, Y, Bn);
        FMA2(Xn, X, A, u);
        MUL2(v, X, B);
        FMA2(Y, Y, A, v);
        X = Xn;
        src = (src + 31) & 31;
        fl  = (fl + 1) & 31;
    }
    {
        int p = (TSTEPS - 1) + ((lane - ((TSTEPS - 1) & 31)) & 31);
        buf[p] = acc;
    }
    __syncthreads();

    for (int q = tid; q < 555; q += 256) {
        float tot = 0.0f;
        #pragma unroll
        for (int w2 = 0; w2 < 8; w2++) {
            int r = q - 32 * w2;
            if (r >= 0 && r < 331) tot += sbuf[w2][r];
        }
        int pos = s0 + q;
        if (pos < SEQ) atomicAdd(&out[i * SEQ + pos], tot);
    }
}

// ---------------------------------------------------------------------------
// Launch — inputs identified by size
// ---------------------------------------------------------------------------
extern "C" void kernel_launch(void* const* d_in, const int* in_sizes, int n_in,
                              void* d_out, int out_size) {
    const float* x  = nullptr;
    const float* W  = nullptr;
    const float* b  = nullptr;
    const float* v1 = nullptr;
    const float* v2 = nullptr;
    for (int idx = 0; idx < n_in; idx++) {
        int sz = in_sizes[idx];
        const float* p = (const float*)d_in[idx];
        if      (sz == SEQ * DM)   x = p;
        else if (sz == DM * NOUT)  W = p;
        else if (sz == NOUT)       b = p;
        else if (sz == DM)         { if (!v1) v1 = p; else v2 = p; }
    }
    float* out = (float*)d_out;
    int full_out = (out_size >= 5 * NM) ? 1 : 0;

    pick_ln_kernel<<<1, 256>>>(v1, v2);
    stats_kernel<<<SEQ, 256>>>(x);
    bprime_kernel<<<NOUT / 32, 256>>>(W, b);
    gemm_kernel<<<dim3(SEQ / BM, NOUT / BN), 256>>>(x, W);
    epi_kernel<<<(NM + 255) / 256, 256>>>(out, full_out);
    zero_kernel<<<(NM + 255) / 256, 256>>>(out);
    spring_kernel<<<dim3(SEQ / 256, NIMU), 256>>>(out);
}

// round 6
// speedup vs baseline: 1.5866x; 1.0671x over previous
#include <cuda_runtime.h>
#include <math.h>
#include <stdint.h>

// ---------------------------------------------------------------------------
// Problem constants
// ---------------------------------------------------------------------------
#define SEQ    4096
#define DM     1024
#define NIMU   72
#define NNOISE 12
#define NOUT   (NIMU * NNOISE)   // 864
#define TSTEPS 300
#define NM     (NIMU * SEQ)      // 294912

// ---------------------------------------------------------------------------
// Scratch (static device globals; no allocation allowed)
// ---------------------------------------------------------------------------
__device__ __align__(16) float  g_mu[SEQ];
__device__ __align__(16) float  g_rstd[SEQ];
__device__ __align__(16) float  g_gamma[DM];
__device__ __align__(16) float  g_beta[DM];
__device__ __align__(16) float  g_bprime[NOUT];
__device__ __align__(16) float  g_p[SEQ * NOUT];           // 14.2 MB
__device__ float2 g_X0[NM], g_Y0[NM], g_A[NM], g_B[NM];    // 9.4 MB

// ---------------------------------------------------------------------------
// Helpers
// ---------------------------------------------------------------------------
typedef unsigned long long ull;

__device__ __forceinline__ ull pk2(float lo, float hi) {
    ull r;
    asm("mov.b64 %0, {%1, %2};" : "=l"(r) : "f"(lo), "f"(hi));
    return r;
}
__device__ __forceinline__ void upk2(float& lo, float& hi, ull v) {
    asm("mov.b64 {%0, %1}, %2;" : "=f"(lo), "=f"(hi) : "l"(v));
}
#define FMA2(d, a, b, c) asm("fma.rn.f32x2 %0, %1, %2, %3;" : "=l"(d) : "l"(a), "l"(b), "l"(c))
#define MUL2(d, a, b)    asm("mul.rn.f32x2 %0, %1, %2;"     : "=l"(d) : "l"(a), "l"(b))

__device__ __forceinline__ float softplus_f(float x) {
    return fmaxf(x, 0.0f) + log1pf(expf(-fabsf(x)));
}
__device__ __forceinline__ float to_tf32(float x) {
    float r;
    asm("cvt.rna.tf32.f32 %0, %1;" : "=f"(r) : "f"(x));
    return r;
}
// m16n8k8 tf32 warp MMA, fp32 accumulate (baseline PTX, sm_80+)
__device__ __forceinline__ void mma8(float* d, const uint32_t* a, uint32_t b0, uint32_t b1) {
    asm volatile(
        "mma.sync.aligned.m16n8k8.row.col.f32.tf32.tf32.f32 "
        "{%0,%1,%2,%3}, {%4,%5,%6,%7}, {%8,%9}, {%0,%1,%2,%3};"
        : "+f"(d[0]), "+f"(d[1]), "+f"(d[2]), "+f"(d[3])
        : "r"(a[0]), "r"(a[1]), "r"(a[2]), "r"(a[3]), "r"(b0), "r"(b1));
}

// ---------------------------------------------------------------------------
// 0) Disambiguate LN vectors (gamma≈ones, beta≈zeros)
// ---------------------------------------------------------------------------
__global__ __launch_bounds__(256) void pick_ln_kernel(const float* __restrict__ a,
                                                      const float* __restrict__ b) {
    __shared__ float sA, sB;
    const int tid = threadIdx.x;
    if (tid == 0) { sA = 0.0f; sB = 0.0f; }
    __syncthreads();
    float la = 0.0f, lb = 0.0f;
    for (int k = tid; k < DM; k += 256) {
        float av = a[k], bv = b[k];
        la += (av - 1.0f) * (av - 1.0f) + bv * bv;
        lb += (bv - 1.0f) * (bv - 1.0f) + av * av;
    }
    #pragma unroll
    for (int o = 16; o > 0; o >>= 1) {
        la += __shfl_down_sync(0xffffffffu, la, o);
        lb += __shfl_down_sync(0xffffffffu, lb, o);
    }
    if ((tid & 31) == 0) { atomicAdd(&sA, la); atomicAdd(&sB, lb); }
    __syncthreads();
    const bool swap = sB < sA;
    for (int k = tid; k < DM; k += 256) {
        g_gamma[k] = swap ? b[k] : a[k];
        g_beta[k]  = swap ? a[k] : b[k];
    }
}

// ---------------------------------------------------------------------------
// 1) Per-token mean / rstd
// ---------------------------------------------------------------------------
__global__ __launch_bounds__(256) void stats_kernel(const float* __restrict__ x) {
    __shared__ float ss[8], ss2[8];
    const int row = blockIdx.x;
    const int tid = threadIdx.x;
    float4 v = reinterpret_cast<const float4*>(x + (size_t)row * DM)[tid];
    float s  = v.x + v.y + v.z + v.w;
    float s2 = v.x * v.x + v.y * v.y + v.z * v.z + v.w * v.w;
    #pragma unroll
    for (int o = 16; o > 0; o >>= 1) {
        s  += __shfl_down_sync(0xffffffffu, s,  o);
        s2 += __shfl_down_sync(0xffffffffu, s2, o);
    }
    if ((tid & 31) == 0) { ss[tid >> 5] = s; ss2[tid >> 5] = s2; }
    __syncthreads();
    if (tid < 8) {
        s = ss[tid]; s2 = ss2[tid];
        #pragma unroll
        for (int o = 4; o > 0; o >>= 1) {
            s  += __shfl_down_sync(0xffu, s,  o);
            s2 += __shfl_down_sync(0xffu, s2, o);
        }
        if (tid == 0) {
            float mu  = s * (1.0f / DM);
            float var = s2 * (1.0f / DM) - mu * mu;
            g_mu[row]   = mu;
            g_rstd[row] = 1.0f / sqrtf(var + 1e-5f);
        }
    }
}

// ---------------------------------------------------------------------------
// 2) bprime[n] = b[n] + sum_k beta[k] * W[k][n]
// ---------------------------------------------------------------------------
__global__ __launch_bounds__(256) void bprime_kernel(const float* __restrict__ W,
                                                     const float* __restrict__ b) {
    __shared__ float sred[8][32];
    const int tid  = threadIdx.x;
    const int lane = tid & 31;
    const int w    = tid >> 5;
    const int col  = blockIdx.x * 32 + lane;
    float acc = 0.0f;
    #pragma unroll 8
    for (int k = w; k < DM; k += 8)
        acc = fmaf(g_beta[k], W[(size_t)k * NOUT + col], acc);
    sred[w][lane] = acc;
    __syncthreads();
    if (w == 0) {
        float tot = b[col];
        #pragma unroll
        for (int j = 0; j < 8; j++) tot += sred[j][lane];
        g_bprime[col] = tot;
    }
}

// ---------------------------------------------------------------------------
// 3) GEMM via mma.sync tf32 (3-pass split), fused LN on A.
//    BM=128, BN=96, BK=32; 8 warps as 4(M)x2(N); warp tile 32x48.
//    Fragments pre-arranged in smem: AH/AL[slot][4], BF[slot][4]={b0h,b1h,b0l,b1l}
//    slotA = (mf*4+ks)*32+lane (mf=row/16), slotB = (nf*4+ks)*32+lane (nf=col/8).
// ---------------------------------------------------------------------------
#define BM 128
#define BN 96
#define BK 32
#define GN_ITER (DM / BK)    // 32
#define SM_AH 0
#define SM_AL 4096
#define SM_BF 8192
#define SM_FLOATS 14336      // 57344 bytes

__global__ __launch_bounds__(256) void gemm_mma_kernel(const float* __restrict__ x,
                                                       const float* __restrict__ W) {
    extern __shared__ float sm[];
    const int tid  = threadIdx.x;
    const int w    = tid >> 5;
    const int lane = tid & 31;
    const int g    = lane >> 2;
    const int tg   = lane & 3;
    const int bm   = blockIdx.x * BM;
    const int bn   = blockIdx.y * BN;

    // producer role: warp handles ks = w&3, mf/nf = 2q + (w>>2)
    const int ksP   = w & 3;
    const int half  = w >> 2;
    // consumer role: warp tile (wm*32 rows) x (wn*48 cols)
    const int wm = w & 3;
    const int wn = w >> 2;

    // hoisted LN stats for producer A rows
    float muA[4][2], rsA[4][2];
    const float* xrow[4][2];
    #pragma unroll
    for (int q = 0; q < 4; q++) {
        int mf = 2 * q + half;
        int m0 = mf * 16 + g, m1 = m0 + 8;
        muA[q][0] = g_mu[bm + m0];  rsA[q][0] = g_rstd[bm + m0];
        muA[q][1] = g_mu[bm + m1];  rsA[q][1] = g_rstd[bm + m1];
        xrow[q][0] = x + (size_t)(bm + m0) * DM;
        xrow[q][1] = x + (size_t)(bm + m1) * DM;
    }

    float acc[2][6][4];
    #pragma unroll
    for (int mi = 0; mi < 2; mi++)
        #pragma unroll
        for (int j = 0; j < 6; j++)
            #pragma unroll
            for (int r = 0; r < 4; r++) acc[mi][j][r] = 0.0f;

    float pvA[4][4], pvB[6][2], pg0, pg1;

    #define FETCH(IT) do {                                                      \
        const int kc0 = (IT) * BK + ksP * 8 + tg;                               \
        const int kc1 = kc0 + 4;                                                \
        pg0 = g_gamma[kc0]; pg1 = g_gamma[kc1];                                 \
        _Pragma("unroll")                                                       \
        for (int q = 0; q < 4; q++) {                                           \
            pvA[q][0] = xrow[q][0][kc0];                                        \
            pvA[q][1] = xrow[q][1][kc0];                                        \
            pvA[q][2] = xrow[q][0][kc1];                                        \
            pvA[q][3] = xrow[q][1][kc1];                                        \
        }                                                                       \
        _Pragma("unroll")                                                       \
        for (int q = 0; q < 6; q++) {                                           \
            int n = bn + (2 * q + half) * 8 + g;                                \
            pvB[q][0] = W[(size_t)kc0 * NOUT + n];                              \
            pvB[q][1] = W[(size_t)kc1 * NOUT + n];                              \
        }                                                                       \
    } while (0)

    #define STORE() do {                                                        \
        _Pragma("unroll")                                                       \
        for (int q = 0; q < 4; q++) {                                           \
            int slot = ((2 * q + half) * 4 + ksP) * 32 + lane;                  \
            float n0 = (pvA[q][0] - muA[q][0]) * rsA[q][0] * pg0;               \
            float n1 = (pvA[q][1] - muA[q][1]) * rsA[q][1] * pg0;               \
            float n2 = (pvA[q][2] - muA[q][0]) * rsA[q][0] * pg1;               \
            float n3 = (pvA[q][3] - muA[q][1]) * rsA[q][1] * pg1;               \
            float4 h, l;                                                        \
            h.x = to_tf32(n0); h.y = to_tf32(n1);                               \
            h.z = to_tf32(n2); h.w = to_tf32(n3);                               \
            l.x = to_tf32(n0 - h.x); l.y = to_tf32(n1 - h.y);                   \
            l.z = to_tf32(n2 - h.z); l.w = to_tf32(n3 - h.w);                   \
            *(float4*)&sm[SM_AH + slot * 4] = h;                                \
            *(float4*)&sm[SM_AL + slot * 4] = l;                                \
        }                                                                       \
        _Pragma("unroll")                                                       \
        for (int q = 0; q < 6; q++) {                                           \
            int slot = ((2 * q + half) * 4 + ksP) * 32 + lane;                  \
            float b0 = pvB[q][0], b1 = pvB[q][1];                               \
            float4 v;                                                           \
            v.x = to_tf32(b0); v.y = to_tf32(b1);                               \
            v.z = to_tf32(b0 - v.x); v.w = to_tf32(b1 - v.y);                   \
            *(float4*)&sm[SM_BF + slot * 4] = v;                                \
        }                                                                       \
    } while (0)

    FETCH(0);
    for (int it = 0; it < GN_ITER; it++) {
        STORE();
        __syncthreads();
        if (it + 1 < GN_ITER) FETCH(it + 1);

        #pragma unroll
        for (int ks = 0; ks < 4; ks++) {
            uint32_t bf[6][4];
            #pragma unroll
            for (int j = 0; j < 6; j++) {
                int slot = ((wn * 6 + j) * 4 + ks) * 32 + lane;
                *(float4*)&bf[j][0] = *(const float4*)&sm[SM_BF + slot * 4];
            }
            #pragma unroll
            for (int mi = 0; mi < 2; mi++) {
                int slot = ((wm * 2 + mi) * 4 + ks) * 32 + lane;
                uint32_t Ah[4], Al[4];
                *(float4*)&Ah[0] = *(const float4*)&sm[SM_AH + slot * 4];
                *(float4*)&Al[0] = *(const float4*)&sm[SM_AL + slot * 4];
                #pragma unroll
                for (int j = 0; j < 6; j++) {
                    mma8(acc[mi][j], Ah, bf[j][0], bf[j][1]);   // Ah*Bh
                    mma8(acc[mi][j], Ah, bf[j][2], bf[j][3]);   // Ah*Bl
                    mma8(acc[mi][j], Al, bf[j][0], bf[j][1]);   // Al*Bh
                }
            }
        }
        __syncthreads();
    }
    #undef FETCH
    #undef STORE

    // Epilogue: + bprime, store. c0/c1: row g, cols 2tg,2tg+1; c2/c3: row g+8.
    #pragma unroll
    for (int mi = 0; mi < 2; mi++) {
        const int row0 = bm + wm * 32 + mi * 16 + g;
        #pragma unroll
        for (int j = 0; j < 6; j++) {
            const int col = bn + wn * 48 + j * 8 + 2 * tg;
            float bp0 = g_bprime[col], bp1 = g_bprime[col + 1];
            *(float2*)&g_p[(size_t)row0 * NOUT + col] =
                make_float2(acc[mi][j][0] + bp0, acc[mi][j][1] + bp1);
            *(float2*)&g_p[(size_t)(row0 + 8) * NOUT + col] =
                make_float2(acc[mi][j][2] + bp0, acc[mi][j][3] + bp1);
        }
    }
}

// ---------------------------------------------------------------------------
// 4) Epilogue: tile 8 seq-rows of p through smem (coalesced), derive spring
//    params + 4 aux outputs.
// ---------------------------------------------------------------------------
__global__ __launch_bounds__(256) void epi_kernel(float* __restrict__ out, int full_out) {
    __shared__ float sp[8 * NOUT];
    const int s0  = blockIdx.x * 8;
    const int tid = threadIdx.x;

    const float4* src = (const float4*)(g_p + (size_t)s0 * NOUT);
    for (int v = tid; v < 8 * NOUT / 4; v += 256)
        ((float4*)sp)[v] = src[v];
    __syncthreads();

    for (int v = tid; v < 8 * NIMU; v += 256) {
        const int i  = v >> 3;
        const int sl = v & 7;
        const int s  = s0 + sl;
        const float* pr = &sp[sl * NOUT];

        float p0  = pr[0 * NIMU + i];
        float p1  = pr[1 * NIMU + i];
        float p2  = pr[2 * NIMU + i];
        float p3  = pr[3 * NIMU + i];
        float c   = pr[4 * NIMU + i];
        float ct  = pr[5 * NIMU + i];
        float phi = pr[6 * NIMU + i];
        float pht = pr[7 * NIMU + i];

        float d  = softplus_f(p1);
        float dt = softplus_f(p3);
        float w1 = sqrtf(softplus_f(p0));   // sqrt(4k-d^2)/2 == sqrt(softplus(p0))
        float w2 = sqrtf(softplus_f(p2));
        float e1 = __expf(-0.5f * d);
        float e2 = __expf(-0.5f * dt);

        float sph, cph, spt, cpt, sw1, cw1, sw2, cw2;
        __sincosf(phi, &sph, &cph);
        __sincosf(pht, &spt, &cpt);
        sincosf(w1, &sw1, &cw1);            // rotation angle: precise (compounds x300)
        sincosf(w2, &sw2, &cw2);

        const int j = i * SEQ + s;
        g_X0[j] = make_float2(c * cph, ct * cpt);
        g_Y0[j] = make_float2(c * sph, ct * spt);
        g_A[j]  = make_float2(e1 * cw1, e2 * cw2);
        g_B[j]  = make_float2(e1 * sw1, e2 * sw2);

        if (full_out) {
            out[1 * NM + j] = pr[8 * NIMU + i];
            out[2 * NM + j] = softplus_f(pr[9 * NIMU + i]);
            out[3 * NM + j] = pr[10 * NIMU + i];
            out[4 * NM + j] = softplus_f(pr[11 * NIMU + i]);
        }
    }
}

// ---------------------------------------------------------------------------
// 5) Zero kinematics region
// ---------------------------------------------------------------------------
__global__ __launch_bounds__(256) void zero_kernel(float* __restrict__ out) {
    int j = blockIdx.x * 256 + threadIdx.x;
    if (j < NM) out[j] = 0.0f;
}

// ---------------------------------------------------------------------------
// 6) Spring + diagonal scatter — rotating-accumulator wavefront (proven R3/R4).
// ---------------------------------------------------------------------------
__global__ __launch_bounds__(256) void spring_kernel(float* __restrict__ out) {
    __shared__ float sbuf[8][336];

    const int i    = blockIdx.y;
    const int s0   = blockIdx.x * 256;
    const int tid  = threadIdx.x;
    const int w    = tid >> 5;
    const int lane = tid & 31;

    const int s   = s0 + w * 32 + lane;
    const int idx = i * SEQ + s;
    float2 x0 = g_X0[idx], y0 = g_Y0[idx], av = g_A[idx], bv = g_B[idx];
    ull X  = pk2(x0.x, x0.y);
    ull Y  = pk2(y0.x, y0.y);
    ull A  = pk2(av.x, av.y);
    ull B  = pk2(bv.x, bv.y);
    ull Bn = pk2(-bv.x, -bv.y);

    float* buf = &sbuf[w][0];
    float acc = 0.0f;
    int   src = lane;
    int   fl  = -1;

    #pragma unroll 4
    for (int t = 0; t < TSTEPS; t++) {
        float lo, hi;
        upk2(lo, hi, Y);
        float c = lo + hi;
        float r = __shfl_sync(0xffffffffu, c, src);
        if (fl == lane) { buf[t - 1] = acc; acc = 0.0f; }
        acc += r;
        ull u, v, Xn;
        MUL2(u, Y, Bn);
        FMA2(Xn, X, A, u);
        MUL2(v, X, B);
        FMA2(Y, Y, A, v);
        X = Xn;
        src = (src + 31) & 31;
        fl  = (fl + 1) & 31;
    }
    {
        int p = (TSTEPS - 1) + ((lane - ((TSTEPS - 1) & 31)) & 31);
        buf[p] = acc;
    }
    __syncthreads();

    for (int q = tid; q < 555; q += 256) {
        float tot = 0.0f;
        #pragma unroll
        for (int w2 = 0; w2 < 8; w2++) {
            int r = q - 32 * w2;
            if (r >= 0 && r < 331) tot += sbuf[w2][r];
        }
        int pos = s0 + q;
        if (pos < SEQ) atomicAdd(&out[i * SEQ + pos], tot);
    }
}

// ---------------------------------------------------------------------------
// Launch — inputs identified by size
// ---------------------------------------------------------------------------
extern "C" void kernel_launch(void* const* d_in, const int* in_sizes, int n_in,
                              void* d_out, int out_size) {
    const float* x  = nullptr;
    const float* W  = nullptr;
    const float* b  = nullptr;
    const float* v1 = nullptr;
    const float* v2 = nullptr;
    for (int idx = 0; idx < n_in; idx++) {
        int sz = in_sizes[idx];
        const float* p = (const float*)d_in[idx];
        if      (sz == SEQ * DM)   x = p;
        else if (sz == DM * NOUT)  W = p;
        else if (sz == NOUT)       b = p;
        else if (sz == DM)         { if (!v1) v1 = p; else v2 = p; }
    }
    float* out = (float*)d_out;
    int full_out = (out_size >= 5 * NM) ? 1 : 0;

    cudaFuncSetAttribute(gemm_mma_kernel,
                         cudaFuncAttributeMaxDynamicSharedMemorySize,
                         SM_FLOATS * (int)sizeof(float));

    pick_ln_kernel<<<1, 256>>>(v1, v2);
    stats_kernel<<<SEQ, 256>>>(x);
    bprime_kernel<<<NOUT / 32, 256>>>(W, b);
    gemm_mma_kernel<<<dim3(SEQ / BM, NOUT / BN), 256,
                      SM_FLOATS * sizeof(float)>>>(x, W);
    epi_kernel<<<SEQ / 8, 256>>>(out, full_out);
    zero_kernel<<<(NM + 255) / 256, 256>>>(out);
    spring_kernel<<<dim3(SEQ / 256, NIMU), 256>>>(out);
}